// round 17
// baseline (speedup 1.0000x reference)
#include <cuda_runtime.h>
#include <cuda_fp16.h>
#include <math.h>
#include <stdint.h>

// ---------------------------------------------------------------------------
// Problem constants
// ---------------------------------------------------------------------------
#define BB   64
#define SS   32
#define HH   1024
#define RR   256
#define DEPTH 9
#define MAXM (BB*512)
#define OSTR (HH + 1)          // output row stride (1025)
#define GHWS_OFF 4718592       // float offset of gh partials inside g_ws

#define SELU_SCALE 1.0507009873554805f
#define SELU_ALPHA 1.6732632423543772f

__device__ __forceinline__ float seluf(float v) {
    return v > 0.f ? SELU_SCALE * v : SELU_SCALE * SELU_ALPHA * expm1f(v);
}
__device__ __forceinline__ float sigmoidf_(float v) {
    return 1.f / (1.f + __expf(-v));
}

// ---------------------------------------------------------------------------
// Scratch (device globals; allocation is forbidden)
// ---------------------------------------------------------------------------
__device__ float g_xcA[(size_t)MAXM * HH];
__device__ float g_xcB[(size_t)MAXM * HH];
__device__ float g_dA[MAXM];
__device__ float g_dB[MAXM];
__device__ float g_y [(size_t)BB * SS * HH];
__device__ float g_ws[(size_t)8388608];          // split-K workspace (32 MB)
__device__ __half g_gif[(size_t)MAXM * 3 * RR];
__device__ __half g_ghf[(size_t)(MAXM/2) * 3 * RR];   // parent-resolution gates
__device__ __half g_xcf16[(size_t)MAXM * HH];
__device__ __half g_hf16A[(size_t)MAXM * RR];
__device__ __half g_hf16B[(size_t)MAXM * RR];
__device__ __half g_sxf[(size_t)BB * SS * HH];
__device__ __half g_lrf[(size_t)MAXM * HH];      // branch out viewed [2M,1024]
// weights
__device__ __half g_Whidh[HH * HH];
__device__ __half g_Whidl[HH * HH];
__device__ __half g_Wbrh[2 * HH * (HH + RR)];
__device__ __half g_Wbrl[2 * HH * (HH + RR)];
__device__ __half g_Wihf[3 * RR * HH];
__device__ __half g_Whhf[3 * RR * RR];

// ---------------------------------------------------------------------------
// mma.sync helpers
// ---------------------------------------------------------------------------
__device__ __forceinline__ void ldsm4(uint32_t* r, const void* p) {
    uint32_t a = (uint32_t)__cvta_generic_to_shared(p);
    asm volatile("ldmatrix.sync.aligned.m8n8.x4.shared.b16 {%0,%1,%2,%3}, [%4];"
        : "=r"(r[0]), "=r"(r[1]), "=r"(r[2]), "=r"(r[3]) : "r"(a));
}
__device__ __forceinline__ void mma_f16(float* d, const uint32_t* a, uint32_t b0, uint32_t b1) {
    asm volatile("mma.sync.aligned.m16n8k16.row.col.f32.f16.f16.f32 "
        "{%0,%1,%2,%3}, {%4,%5,%6,%7}, {%8,%9}, {%0,%1,%2,%3};"
        : "+f"(d[0]), "+f"(d[1]), "+f"(d[2]), "+f"(d[3])
        : "r"(a[0]), "r"(a[1]), "r"(a[2]), "r"(a[3]), "r"(b0), "r"(b1));
}

// ---------------------------------------------------------------------------
// 2-term fp16 GEMM: C[M,N] = epi( A@Wh^T + A[:, :K2]@Wl[:, :K2]^T + bias )
//   DUALA: logical A row = [xc fp16 (1024, stride HH) | hc fp16 (256, stride RR)]
//   OSTRIDE: fp32 output written at row stride OSTR (into d_out)
//   EPI 0: bias   EPI 1: selu   EPI 2: P[r>>1] - selu
// ---------------------------------------------------------------------------
template<int EPI, bool OF32, bool OF16, bool DUALA, bool OSTRIDE>
__global__ __launch_bounds__(256, 2)
void hgemm2(const __half* __restrict__ A, const __half* __restrict__ A2,
            const __half* __restrict__ Wh, const __half* __restrict__ Wl,
            const float* __restrict__ bias,
            float* __restrict__ Cf, __half* __restrict__ Cf16,
            int M, int N, int K, int K2, int ashift, const float* __restrict__ P)
{
    __shared__ __half As[2][128][40];
    __shared__ __half Ws[2][128][40];

    const int tid = threadIdx.x;
    const int warp = tid >> 5, lane = tid & 31;
    const int wm = warp >> 2, wn = warp & 3;
    const int row0 = blockIdx.y * 128, col0 = blockIdx.x * 128;

    const int kt1 = K >> 5;
    const int total = kt1 + (K2 >> 5);

    float acc[4][4][4];
    #pragma unroll
    for (int a = 0; a < 4; a++)
        #pragma unroll
        for (int b = 0; b < 4; b++)
            #pragma unroll
            for (int c = 0; c < 4; c++) acc[a][b][c] = 0.f;

    uint4 ra[2], rw[2];

    auto loadg = [&](int it) {
        int ph = (it >= kt1) ? 1 : 0;
        int k0 = (it - (ph ? kt1 : 0)) << 5;
        const __half* Wp = ph ? Wl : Wh;
        #pragma unroll
        for (int i = 0; i < 2; i++) {
            int u = (i << 8) + tid;
            int r = u >> 2, c = (u & 3) << 3;
            int gr = row0 + r;
            const __half* ap;
            size_t aoff;
            if (DUALA) {
                if (k0 >= HH) { ap = A2; aoff = (size_t)gr * RR + (k0 - HH) + c; }
                else          { ap = A;  aoff = (size_t)gr * HH + k0 + c; }
            } else {
                ap = A; aoff = (size_t)(gr >> ashift) * K + k0 + c;
            }
            ra[i] = (gr < M) ? *(const uint4*)(ap + aoff) : make_uint4(0u, 0u, 0u, 0u);
            rw[i] = *(const uint4*)(Wp + (size_t)(col0 + r) * K + k0 + c);
        }
    };
    auto sts = [&](int buf) {
        #pragma unroll
        for (int i = 0; i < 2; i++) {
            int u = (i << 8) + tid;
            int r = u >> 2, c = (u & 3) << 3;
            *(uint4*)&As[buf][r][c] = ra[i];
            *(uint4*)&Ws[buf][r][c] = rw[i];
        }
    };

    loadg(0);
    sts(0);
    __syncthreads();

    const int a_r = (lane & 15);
    const int a_c = (lane >> 4) << 3;
    const int b_r = (lane & 7) + ((lane >> 4) << 3);
    const int b_c = ((lane >> 3) & 1) << 3;

    for (int it = 0; it < total; ++it) {
        int cur = it & 1;
        bool more = (it + 1 < total);
        if (more) loadg(it + 1);

        #pragma unroll
        for (int s = 0; s < 2; s++) {
            uint32_t afr[4][4], bfr[2][4];
            #pragma unroll
            for (int mt = 0; mt < 4; mt++)
                ldsm4(afr[mt], &As[cur][wm * 64 + mt * 16 + a_r][s * 16 + a_c]);
            #pragma unroll
            for (int p = 0; p < 2; p++)
                ldsm4(bfr[p], &Ws[cur][wn * 32 + p * 16 + b_r][s * 16 + b_c]);
            #pragma unroll
            for (int mt = 0; mt < 4; mt++)
                #pragma unroll
                for (int nt = 0; nt < 4; nt++)
                    mma_f16(acc[mt][nt], afr[mt],
                            bfr[nt >> 1][(nt & 1) * 2], bfr[nt >> 1][(nt & 1) * 2 + 1]);
        }

        if (more) sts(cur ^ 1);
        __syncthreads();
    }

    // ---- epilogue ----
    const int g = lane >> 2, t = lane & 3;
    #pragma unroll
    for (int mt = 0; mt < 4; mt++) {
        #pragma unroll
        for (int half = 0; half < 2; half++) {
            int r = row0 + wm * 64 + mt * 16 + g + half * 8;
            if (r >= M) continue;
            #pragma unroll
            for (int nt = 0; nt < 4; nt++) {
                int c = col0 + wn * 32 + nt * 8 + (t << 1);
                float v0 = acc[mt][nt][half * 2 + 0] + bias[c];
                float v1 = acc[mt][nt][half * 2 + 1] + bias[c + 1];
                if (EPI == 1) { v0 = seluf(v0); v1 = seluf(v1); }
                if (EPI == 2) {
                    float2 p = *(const float2*)(P + (size_t)(r >> 1) * HH + c);
                    v0 = p.x - seluf(v0);
                    v1 = p.y - seluf(v1);
                }
                if (OSTRIDE) {
                    Cf[(size_t)r * OSTR + c]     = v0;
                    Cf[(size_t)r * OSTR + c + 1] = v1;
                } else if (OF32) {
                    *(float2*)(Cf + (size_t)r * N + c) = make_float2(v0, v1);
                }
                if (OF16)
                    *(__half2*)(Cf16 + (size_t)r * N + c) = __floats2half2_rn(v0, v1);
            }
        }
    }
}

// ---------------------------------------------------------------------------
// Split-K GEMM: partial sums to ws[split][M][N], no bias/epilogue.
// ---------------------------------------------------------------------------
template<int TERMS, bool DUALA>
__global__ __launch_bounds__(256, 2)
void hgemm_sk(const __half* __restrict__ A, const __half* __restrict__ A2,
              const __half* __restrict__ Wh, const __half* __restrict__ Wl,
              float* __restrict__ ws,
              int M, int N, int K, int K2, int ashift)
{
    __shared__ __half As[2][128][40];
    __shared__ __half Ws[2][128][40];

    const int tid = threadIdx.x;
    const int warp = tid >> 5, lane = tid & 31;
    const int wm = warp >> 2, wn = warp & 3;
    const int row0 = blockIdx.y * 128, col0 = blockIdx.x * 128;

    const int kt1 = K >> 5;
    const int ktt = (TERMS == 2) ? kt1 + (K2 >> 5) : kt1;
    const int tps = ktt / gridDim.z;
    const int t0 = blockIdx.z * tps, t1 = t0 + tps;

    float acc[4][4][4];
    #pragma unroll
    for (int a = 0; a < 4; a++)
        #pragma unroll
        for (int b = 0; b < 4; b++)
            #pragma unroll
            for (int c = 0; c < 4; c++) acc[a][b][c] = 0.f;

    uint4 ra[2], rw[2];

    auto loadg = [&](int it) {
        int ph = (TERMS == 2 && it >= kt1) ? 1 : 0;
        int k0 = (it - (ph ? kt1 : 0)) << 5;
        const __half* Wp = ph ? Wl : Wh;
        #pragma unroll
        for (int i = 0; i < 2; i++) {
            int u = (i << 8) + tid;
            int r = u >> 2, c = (u & 3) << 3;
            int gr = row0 + r;
            const __half* ap;
            size_t aoff;
            if (DUALA) {
                if (k0 >= HH) { ap = A2; aoff = (size_t)gr * RR + (k0 - HH) + c; }
                else          { ap = A;  aoff = (size_t)gr * HH + k0 + c; }
            } else {
                ap = A; aoff = (size_t)(gr >> ashift) * K + k0 + c;
            }
            ra[i] = (gr < M) ? *(const uint4*)(ap + aoff) : make_uint4(0u, 0u, 0u, 0u);
            rw[i] = *(const uint4*)(Wp + (size_t)(col0 + r) * K + k0 + c);
        }
    };
    auto sts = [&](int buf) {
        #pragma unroll
        for (int i = 0; i < 2; i++) {
            int u = (i << 8) + tid;
            int r = u >> 2, c = (u & 3) << 3;
            *(uint4*)&As[buf][r][c] = ra[i];
            *(uint4*)&Ws[buf][r][c] = rw[i];
        }
    };

    loadg(t0);
    sts(0);
    __syncthreads();

    const int a_r = (lane & 15);
    const int a_c = (lane >> 4) << 3;
    const int b_r = (lane & 7) + ((lane >> 4) << 3);
    const int b_c = ((lane >> 3) & 1) << 3;

    for (int it = t0; it < t1; ++it) {
        int cur = (it - t0) & 1;
        bool more = (it + 1 < t1);
        if (more) loadg(it + 1);

        #pragma unroll
        for (int s = 0; s < 2; s++) {
            uint32_t afr[4][4], bfr[2][4];
            #pragma unroll
            for (int mt = 0; mt < 4; mt++)
                ldsm4(afr[mt], &As[cur][wm * 64 + mt * 16 + a_r][s * 16 + a_c]);
            #pragma unroll
            for (int p = 0; p < 2; p++)
                ldsm4(bfr[p], &Ws[cur][wn * 32 + p * 16 + b_r][s * 16 + b_c]);
            #pragma unroll
            for (int mt = 0; mt < 4; mt++)
                #pragma unroll
                for (int nt = 0; nt < 4; nt++)
                    mma_f16(acc[mt][nt], afr[mt],
                            bfr[nt >> 1][(nt & 1) * 2], bfr[nt >> 1][(nt & 1) * 2 + 1]);
        }

        if (more) sts(cur ^ 1);
        __syncthreads();
    }

    float* wp = ws + (size_t)blockIdx.z * M * N;
    const int g = lane >> 2, t = lane & 3;
    #pragma unroll
    for (int mt = 0; mt < 4; mt++) {
        #pragma unroll
        for (int half = 0; half < 2; half++) {
            int r = row0 + wm * 64 + mt * 16 + g + half * 8;
            if (r >= M) continue;
            #pragma unroll
            for (int nt = 0; nt < 4; nt++) {
                int c = col0 + wn * 32 + nt * 8 + (t << 1);
                *(float2*)(wp + (size_t)r * N + c) =
                    make_float2(acc[mt][nt][half * 2 + 0], acc[mt][nt][half * 2 + 1]);
            }
        }
    }
}

// Combine split-K partials: sum S slices, add bias, apply epilogue.
template<int EPI, bool OF32, bool OF16>
__global__ void sk_combine(const float* __restrict__ ws, int S,
                           const float* __restrict__ bias,
                           float* __restrict__ Cf, __half* __restrict__ Cf16,
                           int M, int N, const float* __restrict__ P)
{
    int i = blockIdx.x * blockDim.x + threadIdx.x;
    if (i >= M * (N >> 1)) return;
    int r = (i << 1) / N, c = (i << 1) % N;
    size_t off = (size_t)r * N + c;
    float2 s = make_float2(0.f, 0.f);
    for (int k = 0; k < S; k++) {
        float2 v = *(const float2*)(ws + (size_t)k * M * N + off);
        s.x += v.x; s.y += v.y;
    }
    float v0 = s.x + bias[c], v1 = s.y + bias[c + 1];
    if (EPI == 1) { v0 = seluf(v0); v1 = seluf(v1); }
    if (EPI == 2) {
        float2 p = *(const float2*)(P + (size_t)(r >> 1) * HH + c);
        v0 = p.x - seluf(v0);
        v1 = p.y - seluf(v1);
    }
    if (OF32) *(float2*)(Cf + off) = make_float2(v0, v1);
    if (OF16) *(__half2*)(Cf16 + off) = __floats2half2_rn(v0, v1);
}

// ---------------------------------------------------------------------------
// Fused GRU + hb + depth. Warp per row, 8 warps/block. All fp16 state.
//   Gates come either from fp16 buffers (Sgi/Sgh == 0, bias already applied)
//   or directly from split-K partials in ws (summed here, bias added here).
//   gh is PARENT-RESOLUTION (row m >> shift; ws slices stride Mp*768).
//   LEAF: depth written to dOut[m*OSTR + 1024] (d_out); no hc out.
// ---------------------------------------------------------------------------
template<bool WRITE_HC, bool LEAF>
__global__ void gru_fused(const __half* __restrict__ gi16, const float* __restrict__ giws,
                          int Sgi, const float* __restrict__ bih,
                          const __half* __restrict__ gh16, const float* __restrict__ ghws,
                          int Sgh, const float* __restrict__ bhh, int Mp,
                          const __half* __restrict__ hPrev, const __half* __restrict__ xc16,
                          const float* __restrict__ Whb, const float* __restrict__ bhb,
                          const float* __restrict__ dPrev, float* __restrict__ dOut,
                          __half* __restrict__ hOut,
                          int M, int shift)
{
    const int m = blockIdx.x * 8 + (threadIdx.x >> 5);
    const int lane = threadIdx.x & 31;
    if (m >= M) return;
    const int p = m >> shift;
    const size_t o  = (size_t)m * 768;
    const size_t og = (size_t)p * 768;
    const size_t hp = (size_t)p * RR;
    const size_t hm = (size_t)m * RR;
    const size_t giStride = (size_t)M * 768;
    const size_t ghStride = (size_t)Mp * 768;

    auto gateGi = [&](int j) -> float {
        if (Sgi == 0) return __half2float(gi16[o + j]);
        float s = bih[j];
        for (int k = 0; k < Sgi; k++) s += giws[k * giStride + o + j];
        return s;
    };
    auto gateGh = [&](int j) -> float {
        if (Sgh == 0) return __half2float(gh16[og + j]);
        float s = bhh[j];
        for (int k = 0; k < Sgh; k++) s += ghws[k * ghStride + og + j];
        return s;
    };

    float v[8];
    #pragma unroll
    for (int u = 0; u < 8; u++) {
        int j = lane + 32 * u;
        float ir = gateGi(j), iz = gateGi(256 + j), inn = gateGi(512 + j);
        float hr = gateGh(j), hz = gateGh(256 + j), hn  = gateGh(512 + j);
        float r = sigmoidf_(ir + hr);
        float z = sigmoidf_(iz + hz);
        float n = tanhf(inn + r * hn);
        float h = __half2float(hPrev[hp + j]);
        float nv = (1.f - z) * n + z * h;
        v[u] = nv;
        if (WRITE_HC) hOut[hm + j] = __float2half(nv);
    }

    // hb dot over [xc(1024, fp16) | hc_new(256)]
    const uint4* xr = (const uint4*)(xc16 + (size_t)m * HH);
    const float4* w4 = (const float4*)Whb;
    float s = 0.f;
    #pragma unroll
    for (int it = 0; it < 4; it++) {
        int i = lane + 32 * it;
        uint4 uu = xr[i];
        __half2 p0 = *(__half2*)&uu.x, p1 = *(__half2*)&uu.y;
        __half2 p2 = *(__half2*)&uu.z, p3 = *(__half2*)&uu.w;
        float4 wa = w4[2 * i], wb = w4[2 * i + 1];
        s += __low2float(p0) * wa.x + __high2float(p0) * wa.y
           + __low2float(p1) * wa.z + __high2float(p1) * wa.w;
        s += __low2float(p2) * wb.x + __high2float(p2) * wb.y
           + __low2float(p3) * wb.z + __high2float(p3) * wb.w;
    }
    #pragma unroll
    for (int u = 0; u < 8; u++) {
        int j = lane + 32 * u;
        s += v[u] * Whb[1024 + j];
    }
    #pragma unroll
    for (int off = 16; off; off >>= 1) s += __shfl_xor_sync(0xffffffffu, s, off);
    if (lane == 0) {
        float dv = dPrev[p] + sigmoidf_(s + bhb[0]);
        if (LEAF) dOut[(size_t)m * OSTR + HH] = dv;
        else      dOut[m] = dv;
    }
}

// ---------------------------------------------------------------------------
// Misc elementwise kernels
// ---------------------------------------------------------------------------
__global__ void half_split_kernel(const float* __restrict__ in, __half* __restrict__ h,
                                  __half* __restrict__ l, int n) {
    int i = blockIdx.x * blockDim.x + threadIdx.x;
    if (i < n) {
        __half hv = __float2half(in[i]);
        h[i] = hv;
        l[i] = __float2half(in[i] - __half2float(hv));
    }
}
__global__ void half_cast_kernel(const float* __restrict__ in, __half* __restrict__ out, int n) {
    int i = blockIdx.x * blockDim.x + threadIdx.x;
    if (i < n) out[i] = __float2half(in[i]);
}
__global__ void selu_half_kernel(const float* __restrict__ in, __half* __restrict__ out, int n) {
    int i = blockIdx.x * blockDim.x + threadIdx.x;
    if (i < n) out[i] = __float2half(seluf(in[i]));
}
__global__ void mean_kernel(const float* __restrict__ y, float* __restrict__ xc,
                            __half* __restrict__ xf16) {
    int i = blockIdx.x * blockDim.x + threadIdx.x;
    if (i >= BB * HH) return;
    int b = i >> 10, h = i & (HH - 1);
    float s = 0.f;
    #pragma unroll 8
    for (int t = 0; t < SS; t++) s += y[((size_t)(b * SS + t)) * HH + h];
    float v = s * (1.f / SS);
    xc[i] = v;
    xf16[i] = __float2half(v);
}
__global__ void zero32_kernel(uint32_t* p, int n) {
    int i = blockIdx.x * blockDim.x + threadIdx.x;
    if (i < n) p[i] = 0u;
}

// ---------------------------------------------------------------------------
// Host driver (graph-capturable: only kernel launches)
// ---------------------------------------------------------------------------
static inline int cdiv(int a, int b) { return (a + b - 1) / b; }

extern "C" void kernel_launch(void* const* d_in, const int* in_sizes, int n_in,
                              void* d_out, int out_size)
{
    const float* x        = (const float*)d_in[0];
    const float* W_hidden = (const float*)d_in[1];
    const float* b_hidden = (const float*)d_in[2];
    const float* W_hb     = (const float*)d_in[3];
    const float* b_hb     = (const float*)d_in[4];
    const float* W_branch = (const float*)d_in[5];
    const float* b_branch = (const float*)d_in[6];
    const float* W_ih     = (const float*)d_in[7];
    const float* W_hh     = (const float*)d_in[8];
    const float* b_ih     = (const float*)d_in[9];
    const float* b_hh     = (const float*)d_in[10];

    float *xcA, *xcB, *dA, *dB, *y, *ws;
    __half *gif, *ghf, *xcf16, *hf16A, *hf16B, *sxf, *lrf;
    __half *Whidh, *Whidl, *Wbrh, *Wbrl, *Wihf, *Whhf;

    cudaGetSymbolAddress((void**)&xcA, g_xcA);   cudaGetSymbolAddress((void**)&xcB, g_xcB);
    cudaGetSymbolAddress((void**)&dA,  g_dA);    cudaGetSymbolAddress((void**)&dB,  g_dB);
    cudaGetSymbolAddress((void**)&y,   g_y);     cudaGetSymbolAddress((void**)&ws,  g_ws);
    cudaGetSymbolAddress((void**)&gif, g_gif);   cudaGetSymbolAddress((void**)&ghf, g_ghf);
    cudaGetSymbolAddress((void**)&xcf16, g_xcf16);
    cudaGetSymbolAddress((void**)&hf16A, g_hf16A); cudaGetSymbolAddress((void**)&hf16B, g_hf16B);
    cudaGetSymbolAddress((void**)&sxf, g_sxf);
    cudaGetSymbolAddress((void**)&lrf, g_lrf);
    cudaGetSymbolAddress((void**)&Whidh, g_Whidh); cudaGetSymbolAddress((void**)&Whidl, g_Whidl);
    cudaGetSymbolAddress((void**)&Wbrh, g_Wbrh);   cudaGetSymbolAddress((void**)&Wbrl, g_Wbrl);
    cudaGetSymbolAddress((void**)&Wihf, g_Wihf);   cudaGetSymbolAddress((void**)&Whhf, g_Whhf);

    float* ghws = ws + GHWS_OFF;
    const int nsx = BB * SS * HH;

    // ---- weight prep ----
    half_split_kernel<<<cdiv(HH*HH, 256), 256>>>(W_hidden, Whidh, Whidl, HH*HH);
    half_split_kernel<<<cdiv(2*HH*(HH+RR), 256), 256>>>(W_branch, Wbrh, Wbrl, 2*HH*(HH+RR));
    half_cast_kernel<<<cdiv(3*RR*HH, 256), 256>>>(W_ih, Wihf, 3*RR*HH);
    half_cast_kernel<<<cdiv(3*RR*RR, 256), 256>>>(W_hh, Whhf, 3*RR*RR);

    // ---- root: xc0 = mean_s selu(selu(x) @ W_hidden^T + b_hidden) ----
    selu_half_kernel<<<cdiv(nsx, 256), 256>>>(x, sxf, nsx);
    hgemm2<1, true, false, false, false><<<dim3(HH/128, (BB*SS)/128), 256>>>(
        sxf, sxf, Whidh, Whidl, b_hidden, y, nullptr, BB*SS, HH, HH, HH, 0, nullptr);
    mean_kernel<<<cdiv(BB*HH, 256), 256>>>(y, xcA, xcf16);

    zero32_kernel<<<cdiv(BB*RR/2, 256), 256>>>((uint32_t*)hf16A, BB*RR/2);
    zero32_kernel<<<1, 64>>>((uint32_t*)dA, BB);

    // ---- levels 0 .. DEPTH-1 ----
    for (int d = 0; d < DEPTH; d++) {
        int M  = BB << d;
        int M2 = M << 1;
        int gy = cdiv(M, 128);
        int shift = (d == 0) ? 0 : 1;
        int Mp = M >> shift;
        int S = (d <= 3) ? 8 : ((d == 4) ? 4 : 2);
        const int Sgh = 4;

        if (d <= 6) {
            // gi partials -> ws (summed inside gru_fused)
            hgemm_sk<1, false><<<dim3(6, gy, S), 256>>>(
                xcf16, xcf16, Wihf, Wihf, ws, M, 768, HH, 0, 0);
        } else {
            hgemm2<0, false, true, false, false><<<dim3(6, gy), 256>>>(
                xcf16, xcf16, Wihf, Wihf, b_ih, nullptr, gif, M, 768, HH, 0, 0, nullptr);
        }

        if (d <= 5) {
            // gh partials at parent resolution -> ghws (summed inside gru_fused)
            hgemm_sk<1, false><<<dim3(6, cdiv(Mp, 128), Sgh), 256>>>(
                hf16A, hf16A, Whhf, Whhf, ghws, Mp, 768, RR, 0, 0);
        } else {
            hgemm2<0, false, true, false, false><<<dim3(6, cdiv(Mp, 128)), 256>>>(
                hf16A, hf16A, Whhf, Whhf, b_hh, nullptr, ghf, Mp, 768, RR, 0, 0, nullptr);
        }

        // GRU + hb + depth
        {
            int Sgi_eff = (d <= 6) ? S : 0;
            int Sgh_eff = (d <= 5) ? Sgh : 0;
            gru_fused<true, false><<<cdiv(M, 8), 256>>>(
                gif, ws, Sgi_eff, b_ih,
                ghf, ghws, Sgh_eff, b_hh, Mp,
                hf16A, xcf16, W_hb, b_hb, dA, dB, hf16B, M, shift);
        }

        // branch -> fp16 lr. lo term kept at d<=3 only.
        if (d <= 5) {
            if (d <= 3)
                hgemm_sk<2, true><<<dim3(16, gy, S), 256>>>(
                    xcf16, hf16B, Wbrh, Wbrl, ws, M, 2*HH, HH+RR, HH, 0);
            else
                hgemm_sk<1, true><<<dim3(16, gy, S), 256>>>(
                    xcf16, hf16B, Wbrh, Wbrl, ws, M, 2*HH, HH+RR, 0, 0);
            sk_combine<1, false, true><<<cdiv(M*2*HH/2, 256), 256>>>(
                ws, S, b_branch, nullptr, lrf, M, 2*HH, nullptr);
        } else {
            hgemm2<1, false, true, true, false><<<dim3(16, gy), 256>>>(
                xcf16, hf16B, Wbrh, Wbrl, b_branch, nullptr, lrf,
                M, 2*HH, HH+RR, 0, 0, nullptr);
        }

        // child = xc[parent] - selu(lr @ Whid_hi^T + b)
        if (d <= 5) {
            hgemm_sk<1, false><<<dim3(8, cdiv(M2, 128), S), 256>>>(
                lrf, lrf, Whidh, Whidh, ws, M2, HH, HH, 0, 0);
            sk_combine<2, true, true><<<cdiv(M2*HH/2, 256), 256>>>(
                ws, S, b_hidden, xcB, xcf16, M2, HH, xcA);
        } else if (d <= 7) {
            hgemm2<2, true, true, false, false><<<dim3(8, cdiv(M2, 128)), 256>>>(
                lrf, lrf, Whidh, Whidh, b_hidden, xcB, xcf16, M2, HH, HH, 0, 0, xcA);
        } else {
            hgemm2<2, false, true, false, true><<<dim3(8, M2/128), 256>>>(
                lrf, lrf, Whidh, Whidh, b_hidden, (float*)d_out, xcf16,
                M2, HH, HH, 0, 0, xcA);
        }

        float* t; __half* ht;
        t = xcA; xcA = xcB; xcB = t;
        t = dA;  dA  = dB;  dB  = t;
        ht = hf16A; hf16A = hf16B; hf16B = ht;
    }

    // ---- leaf step (M = 32768): GRU gates + depth into d_out ----
    {
        int M = MAXM;
        int Mp = M >> 1;
        int gy = M / 128;
        hgemm2<0, false, true, false, false><<<dim3(6, gy), 256>>>(
            xcf16, xcf16, Wihf, Wihf, b_ih, nullptr, gif, M, 768, HH, 0, 0, nullptr);
        hgemm2<0, false, true, false, false><<<dim3(6, Mp/128), 256>>>(
            hf16A, hf16A, Whhf, Whhf, b_hh, nullptr, ghf, Mp, 768, RR, 0, 0, nullptr);
        gru_fused<false, true><<<cdiv(M, 8), 256>>>(
            gif, ws, 0, b_ih,
            ghf, ws, 0, b_hh, Mp,
            hf16A, xcf16, W_hb, b_hb, dA, (float*)d_out, nullptr, M, 1);
    }
}